// round 1
// baseline (speedup 1.0000x reference)
#include <cuda_runtime.h>
#include <cstdint>
#include <cstddef>

// ---------------------------------------------------------------------------
// GCN_21569325760838: 2-layer GCN
//   h1 = x @ W1 ; a1 = relu(Agg(h1) + b1)
//   h2 = a1 @ W2 ; out = Agg(h2) + b2
// Agg(h)[d] = sum_{e: dst=d} dinv[src]*dinv[d]*h[src] + dinv[d]^2 * h[d]
// deg[v] = (#edges with dst==v) + 1 ; dinv = rsqrt(deg)
// ---------------------------------------------------------------------------

#define NMAX 100000
#define NF1  128
#define NF2  64

__device__ int   g_is64;
__device__ int   g_deg [NMAX];
__device__ float g_dinv[NMAX];
__device__ float g_h1  [(size_t)NMAX * NF1];   // x @ W1
__device__ float g_agg1[(size_t)NMAX * NF1];   // aggregated, then relu+bias in place
__device__ float g_h2  [(size_t)NMAX * NF2];   // a1 @ W2

// ---------------------------------------------------------------------------
__global__ void k_set_flag() { g_is64 = 1; }

// Deterministic dtype probe: reinterpret first nscan entries as int64.
// Real int64 indices are in [0, N); int32 data read as int64 is >= 2^32
// except when the odd word happens to be 0 (prob ~1e-5 per sample).
__global__ void k_detect(const long long* __restrict__ p, int nscan, int n_nodes) {
    int i = blockIdx.x * blockDim.x + threadIdx.x;
    if (i < nscan) {
        long long v = p[i];
        if (v < 0 || v >= (long long)n_nodes) g_is64 = 0;
    }
}

__device__ __forceinline__ void load_edge(const void* eidx, int e, int E, int& s, int& d) {
    if (g_is64) {
        const long long* p = (const long long*)eidx;
        s = (int)p[e]; d = (int)p[(size_t)E + e];
    } else {
        const int* p = (const int*)eidx;
        s = p[e]; d = p[(size_t)E + e];
    }
}

// ---------------------------------------------------------------------------
__global__ void k_deg_init(int n) {
    int i = blockIdx.x * blockDim.x + threadIdx.x;
    if (i < n) g_deg[i] = 1;   // self loop
}

__global__ void k_deg(const void* __restrict__ eidx, int E) {
    int e = blockIdx.x * blockDim.x + threadIdx.x;
    if (e >= E) return;
    int s, d;
    load_edge(eidx, e, E, s, d);
    atomicAdd(&g_deg[d], 1);
}

__global__ void k_dinv(int n) {
    int i = blockIdx.x * blockDim.x + threadIdx.x;
    if (i < n) g_dinv[i] = rsqrtf((float)g_deg[i]);
}

// ---------------------------------------------------------------------------
// Simple fp32 tiled GEMM, row-major: C[M,N] = A[M,K] @ B[K,N].  N == BN.
template<int BM, int BN, int BK, int TM, int TN>
__global__ void gemm_rrr(const float* __restrict__ A, const float* __restrict__ B,
                         float* __restrict__ C, int M, int K) {
    __shared__ float As[BM][BK + 4];
    __shared__ float Bs[BK][BN];
    constexpr int NT = (BM / TM) * (BN / TN);
    const int tx = threadIdx.x % (BN / TN);
    const int ty = threadIdx.x / (BN / TN);
    const int row0 = blockIdx.x * BM;

    float acc[TM][TN];
    #pragma unroll
    for (int i = 0; i < TM; i++)
        #pragma unroll
        for (int j = 0; j < TN; j++) acc[i][j] = 0.f;

    for (int k0 = 0; k0 < K; k0 += BK) {
        // A tile: BM x BK (float4 loads)
        #pragma unroll
        for (int i = threadIdx.x; i < BM * BK / 4; i += NT) {
            int r = i / (BK / 4), c4 = i % (BK / 4);
            float4 v = make_float4(0.f, 0.f, 0.f, 0.f);
            if (row0 + r < M)
                v = ((const float4*)(A + (size_t)(row0 + r) * K + k0))[c4];
            *((float4*)&As[r][c4 * 4]) = v;
        }
        // B tile: BK x BN
        #pragma unroll
        for (int i = threadIdx.x; i < BK * BN / 4; i += NT) {
            int r = i / (BN / 4), c4 = i % (BN / 4);
            *((float4*)&Bs[r][c4 * 4]) =
                ((const float4*)(B + (size_t)(k0 + r) * BN))[c4];
        }
        __syncthreads();
        #pragma unroll
        for (int k = 0; k < BK; k++) {
            float a[TM], b[TN];
            #pragma unroll
            for (int i = 0; i < TM; i++) a[i] = As[ty * TM + i][k];
            #pragma unroll
            for (int j = 0; j < TN; j++) b[j] = Bs[k][tx * TN + j];
            #pragma unroll
            for (int i = 0; i < TM; i++)
                #pragma unroll
                for (int j = 0; j < TN; j++) acc[i][j] += a[i] * b[j];
        }
        __syncthreads();
    }
    #pragma unroll
    for (int i = 0; i < TM; i++) {
        int r = row0 + ty * TM + i;
        if (r < M) {
            #pragma unroll
            for (int j = 0; j < TN; j += 4) {
                float4 v = make_float4(acc[i][j], acc[i][j+1], acc[i][j+2], acc[i][j+3]);
                ((float4*)(C + (size_t)r * BN))[(tx * TN + j) / 4] = v;
            }
        }
    }
}

// ---------------------------------------------------------------------------
// Self-loop init, layer 1: agg1[i][:] = dinv[i]^2 * h1[i][:]
__global__ void k_self1(int n) {
    int idx = blockIdx.x * blockDim.x + threadIdx.x;   // one float4 each
    int node = idx / (NF1 / 4);
    if (node >= n) return;
    float w = g_dinv[node]; w *= w;
    float4 v = ((const float4*)g_h1)[idx];
    v.x *= w; v.y *= w; v.z *= w; v.w *= w;
    ((float4*)g_agg1)[idx] = v;
}

// Edge scatter, layer 1: one warp per edge, 32 lanes x float4 = 128 feats.
__global__ void k_edge1(const void* __restrict__ eidx, int E) {
    int e = blockIdx.x * (blockDim.x / 32) + (threadIdx.x >> 5);
    if (e >= E) return;
    int lane = threadIdx.x & 31;
    int s, d;
    load_edge(eidx, e, E, s, d);
    float norm = g_dinv[s] * g_dinv[d];
    float4 v = ((const float4*)(g_h1 + (size_t)s * NF1))[lane];
    v.x *= norm; v.y *= norm; v.z *= norm; v.w *= norm;
    float* op = g_agg1 + (size_t)d * NF1 + lane * 4;
    asm volatile("red.global.add.v4.f32 [%0], {%1,%2,%3,%4};"
                 :: "l"(op), "f"(v.x), "f"(v.y), "f"(v.z), "f"(v.w) : "memory");
}

// relu(agg1 + b1) in place
__global__ void k_relu_bias(const float* __restrict__ b1, int n) {
    int idx = blockIdx.x * blockDim.x + threadIdx.x;
    int node = idx / (NF1 / 4);
    if (node >= n) return;
    int c4 = idx % (NF1 / 4);
    float4 v = ((float4*)g_agg1)[idx];
    float4 b = ((const float4*)b1)[c4];
    v.x = fmaxf(v.x + b.x, 0.f);
    v.y = fmaxf(v.y + b.y, 0.f);
    v.z = fmaxf(v.z + b.z, 0.f);
    v.w = fmaxf(v.w + b.w, 0.f);
    ((float4*)g_agg1)[idx] = v;
}

// Self-loop init + bias, layer 2, writes directly to d_out
__global__ void k_self2(float* __restrict__ out, const float* __restrict__ b2, int n) {
    int idx = blockIdx.x * blockDim.x + threadIdx.x;
    int node = idx / (NF2 / 4);
    if (node >= n) return;
    int c4 = idx % (NF2 / 4);
    float w = g_dinv[node]; w *= w;
    float4 v = ((const float4*)g_h2)[idx];
    float4 b = ((const float4*)b2)[c4];
    v.x = v.x * w + b.x;
    v.y = v.y * w + b.y;
    v.z = v.z * w + b.z;
    v.w = v.w * w + b.w;
    ((float4*)out)[idx] = v;
}

// Edge scatter, layer 2: 16 lanes per edge (64 feats).
__global__ void k_edge2(const void* __restrict__ eidx, float* __restrict__ out, int E) {
    int idx = blockIdx.x * blockDim.x + threadIdx.x;
    int e = idx >> 4;
    if (e >= E) return;
    int lane = idx & 15;
    int s, d;
    load_edge(eidx, e, E, s, d);
    float norm = g_dinv[s] * g_dinv[d];
    float4 v = ((const float4*)(g_h2 + (size_t)s * NF2))[lane];
    v.x *= norm; v.y *= norm; v.z *= norm; v.w *= norm;
    float* op = out + (size_t)d * NF2 + lane * 4;
    asm volatile("red.global.add.v4.f32 [%0], {%1,%2,%3,%4};"
                 :: "l"(op), "f"(v.x), "f"(v.y), "f"(v.z), "f"(v.w) : "memory");
}

// ---------------------------------------------------------------------------
extern "C" void kernel_launch(void* const* d_in, const int* in_sizes, int n_in,
                              void* d_out, int out_size) {
    const void*  eidx = d_in[0];
    const float* x    = (const float*)d_in[1];
    const float* W1   = (const float*)d_in[2];
    const float* b1   = (const float*)d_in[3];
    const float* W2   = (const float*)d_in[4];
    const float* b2   = (const float*)d_in[5];
    float* out = (float*)d_out;

    const int E = in_sizes[0] / 2;
    const int N = in_sizes[1] / NF1;

    float *p_h1, *p_agg1, *p_h2;
    cudaGetSymbolAddress((void**)&p_h1,   g_h1);
    cudaGetSymbolAddress((void**)&p_agg1, g_agg1);
    cudaGetSymbolAddress((void**)&p_h2,   g_h2);

    // dtype probe
    k_set_flag<<<1, 1>>>();
    int nscan = E < 2048 ? E : 2048;
    k_detect<<<(nscan + 255) / 256, 256>>>((const long long*)eidx, nscan, N);

    // degrees
    k_deg_init<<<(N + 255) / 256, 256>>>(N);
    k_deg<<<(E + 255) / 256, 256>>>(eidx, E);
    k_dinv<<<(N + 255) / 256, 256>>>(N);

    // layer 1
    gemm_rrr<64, 128, 32, 4, 8><<<(N + 63) / 64, 256>>>(x, W1, p_h1, N, NF1);
    k_self1<<<(N * (NF1 / 4) + 255) / 256, 256>>>(N);
    k_edge1<<<(E + 7) / 8, 256>>>(eidx, E);
    k_relu_bias<<<(N * (NF1 / 4) + 255) / 256, 256>>>(b1, N);

    // layer 2
    gemm_rrr<64, 64, 32, 4, 4><<<(N + 63) / 64, 256>>>(p_agg1, W2, p_h2, N, NF1);
    k_self2<<<(N * (NF2 / 4) + 255) / 256, 256>>>(out, b2, N);
    k_edge2<<<((size_t)E * 16 + 255) / 256, 256>>>(eidx, out, E);
}